// round 14
// baseline (speedup 1.0000x reference)
#include <cuda_runtime.h>

// ---------------------------------------------------------------------------
// DNN_KalmanNet_SLAM — fused, latency-optimized. Geometry: 10 x 512.
// R14 change: W1 staged into shared TRANSPOSED via coalesced float4 loads,
// l1 computed from conflict-free smem (kills the 14-wavefront-per-LDG
// replay storm of the old row-major scalar reads). s_big is time-multiplexed:
// W1^T for all blocks during stage A, then W2a/W2b for the head block.
// ---------------------------------------------------------------------------

#define NB     10
#define NT     512
#define WPB    16
#define H1     560
#define GH     145
#define HEADB  (NB - 1)

__device__ float    g_h0[GH];
__device__ float    g_h1[GH];
__device__ unsigned g_cnt  = 0;
__device__ unsigned g_gen  = 0;
__device__ unsigned g_cnt2 = 0;

__device__ __forceinline__ float wsum(float v) {
#pragma unroll
    for (int o = 16; o; o >>= 1) v += __shfl_down_sync(0xffffffffu, v, o);
    return v;
}
__device__ __forceinline__ float sigm(float x) { return 1.0f / (1.0f + __expf(-x)); }
__device__ __forceinline__ float tanha(float x) {
    float y; asm("tanh.approx.f32 %0, %1;" : "=f"(y) : "f"(x)); return y;
}

__device__ __forceinline__ void gbar1() {
    __threadfence();
    __syncthreads();
    if (threadIdx.x == 0) {
        volatile unsigned* gp = &g_gen;
        unsigned my = *gp;
        if (atomicAdd(&g_cnt, 1u) == NB - 1u) {
            g_cnt = 0;
            __threadfence();
            atomicAdd(&g_gen, 1u);
        } else {
            while (*gp == my) { }
        }
    }
    __syncthreads();
    __threadfence();
}

__global__ __launch_bounds__(NT, 1)
void kalmannet_kernel(
    const float* __restrict__ state_inno, const float* __restrict__ obs_inno,
    const float* __restrict__ diff_state, const float* __restrict__ diff_obs,
    const float* __restrict__ W1,   const float* __restrict__ b1,
    const float* __restrict__ Wih0, const float* __restrict__ Whh0,
    const float* __restrict__ bih0, const float* __restrict__ bhh0,
    const float* __restrict__ Wih1, const float* __restrict__ Whh1,
    const float* __restrict__ bih1, const float* __restrict__ bhh1,
    const float* __restrict__ W2a,  const float* __restrict__ b2a,
    const float* __restrict__ W2b,  const float* __restrict__ b2b,
    const float* __restrict__ hn,
    float* __restrict__ out)
{
    __shared__ __align__(16) float s_l1[H1];
    __shared__ float s_x[16];
    __shared__ float s_hn[2 * GH];
    __shared__ float s_v[GH + 8];
    __shared__ float s_hid[40];
    __shared__ float s_b2a[40];
    __shared__ float s_b2b[10];
    // Time-multiplexed: [stage A] W1^T as s_big[k*560 + r] (7840 floats)
    //                   [post-l1, head block] W2a (5800) + W2b (400)
    __shared__ __align__(16) float s_big[14 * H1];
    float* s_w2a = s_big;          // 5800 floats
    float* s_w2b = s_big + 5800;   // 400 floats

    const int t    = threadIdx.x;
    const int lane = t & 31;
    const int lw   = t >> 5;
    const int e    = blockIdx.x * WPB + lw;
    const bool act = (e < GH);

    // ---- inputs ----
    if (t < 14) {
        float v;
        if      (t < 5)  v = state_inno[t];
        else if (t < 7)  v = obs_inno[t - 5];
        else if (t < 12) v = diff_state[t - 7];
        else             v = diff_obs[t - 12];
        s_x[t] = v;
    }
    for (int i = t; i < 2 * GH; i += NT) s_hn[i] = __ldg(hn + i);

    // ---- stage W1 transposed into smem (coalesced float4 reads) ----
    {
        const float4* w1v = (const float4*)W1;   // 7840 floats = 1960 float4
#pragma unroll
        for (int base = 0; base < 1960; base += NT) {
            int i = base + t;
            if (i < 1960) {
                float4 v = __ldg(w1v + i);
                int j = 4 * i;
                s_big[(j % 14) * H1 + (j / 14)]             = v.x;
                s_big[((j + 1) % 14) * H1 + ((j + 1) / 14)] = v.y;
                s_big[((j + 2) % 14) * H1 + ((j + 2) / 14)] = v.z;
                s_big[((j + 3) % 14) * H1 + ((j + 3) / 14)] = v.w;
            }
        }
    }
    __syncthreads();   // s_x, s_hn, W1^T ready

    // ---- l1 from smem (conflict-free LDS, lane stride 4B) ----
    for (int r = t; r < H1; r += NT) {
        float s = b1[r];
#pragma unroll
        for (int k = 0; k < 14; k++) s = fmaf(s_big[k * H1 + r], s_x[k], s);
        s_l1[r] = fmaxf(s, 0.0f);
    }

    // ---- prefetch Wih1 rows into registers (independent of h0) ----
    float w1r[5], w1z[5], w1n[5];
    if (act) {
        const float* pr = Wih1 + e * GH;
        const float* pz = Wih1 + (e + GH) * GH;
        const float* pn = Wih1 + (e + 2 * GH) * GH;
#pragma unroll
        for (int i = 0; i < 5; i++) {
            int k = lane + 32 * i;
            bool ok = (k < GH);
            w1r[i] = ok ? __ldg(pr + k) : 0.f;
            w1z[i] = ok ? __ldg(pz + k) : 0.f;
            w1n[i] = ok ? __ldg(pn + k) : 0.f;
        }
    }

    // ---- recurrent dots for BOTH layers (independent of l1/h0) ----
    float A0 = 0.f, A1 = 0.f, A2 = 0.f;
    float B0 = 0.f, B1 = 0.f, B2 = 0.f;
    float bi0r = 0.f, bi0z = 0.f, bi0n = 0.f;
    float bi1r = 0.f, bi1z = 0.f, bi1n = 0.f;
    if (act) {
        const float* q0r = Whh0 + e * GH;
        const float* q0z = Whh0 + (e + GH) * GH;
        const float* q0n = Whh0 + (e + 2 * GH) * GH;
        const float* q1r = Whh1 + e * GH;
        const float* q1z = Whh1 + (e + GH) * GH;
        const float* q1n = Whh1 + (e + 2 * GH) * GH;
#pragma unroll 5
        for (int k = lane; k < GH; k += 32) {
            float h0v = s_hn[k], h1v = s_hn[GH + k];
            A0 = fmaf(q0r[k], h0v, A0);
            A1 = fmaf(q0z[k], h0v, A1);
            A2 = fmaf(q0n[k], h0v, A2);
            B0 = fmaf(q1r[k], h1v, B0);
            B1 = fmaf(q1z[k], h1v, B1);
            B2 = fmaf(q1n[k], h1v, B2);
        }
        A0 = wsum(A0); A1 = wsum(A1); A2 = wsum(A2);
        B0 = wsum(B0); B1 = wsum(B1); B2 = wsum(B2);
        if (lane == 0) {
            A0 += bhh0[e];  A1 += bhh0[e + GH];  A2 += bhh0[e + 2 * GH];
            B0 += bhh1[e];  B1 += bhh1[e + GH];  B2 += bhh1[e + 2 * GH];
            bi0r = bih0[e]; bi0z = bih0[e + GH]; bi0n = bih0[e + 2 * GH];
            bi1r = bih1[e]; bi1z = bih1[e + GH]; bi1n = bih1[e + 2 * GH];
        }
    }
    __syncthreads();   // s_l1 final; s_big (W1^T) no longer needed

    // ---- head block: idle warps now overwrite s_big with head weights ----
    if (blockIdx.x == HEADB && lw >= 1) {
        const float4* av = (const float4*)W2a;   // 5800 floats = 1450 float4
        for (int i = (t - 32); i < 1450; i += NT - 32) {
            float4 v = __ldg(av + i);
            s_w2a[4 * i]     = v.x;
            s_w2a[4 * i + 1] = v.y;
            s_w2a[4 * i + 2] = v.z;
            s_w2a[4 * i + 3] = v.w;
        }
        if (lw == 1) {
            if (lane < 10) s_b2b[lane] = b2b[lane];
            for (int i = lane; i < 40; i += 32) s_b2a[i] = b2a[i];
        }
        if (lw >= 2) {
            const float4* bv = (const float4*)W2b;   // 400 floats = 100 float4
            for (int i = (t - 64); i < 100; i += NT - 64) {
                float4 v = __ldg(bv + i);
                s_w2b[4 * i]     = v.x;
                s_w2b[4 * i + 1] = v.y;
                s_w2b[4 * i + 2] = v.z;
                s_w2b[4 * i + 3] = v.w;
            }
        }
    }

    // ---- GRU layer 0: Wih0 @ l1, float4 loads ----
    if (act) {
        const float4* xr = (const float4*)s_l1;
        const float4* wr = (const float4*)(Wih0 + e * H1);
        const float4* wz = (const float4*)(Wih0 + (e + GH) * H1);
        const float4* wn = (const float4*)(Wih0 + (e + 2 * GH) * H1);
        float sr = 0.f, sz = 0.f, sn = 0.f;
#pragma unroll
        for (int i = 0; i < 5; i++) {
            int k = lane + 32 * i;
            if (k < H1 / 4) {
                float4 x = xr[k];
                float4 a = wr[k];
                sr += a.x * x.x + a.y * x.y + a.z * x.z + a.w * x.w;
                float4 b = wz[k];
                sz += b.x * x.x + b.y * x.y + b.z * x.z + b.w * x.w;
                float4 c = wn[k];
                sn += c.x * x.x + c.y * x.y + c.z * x.z + c.w * x.w;
            }
        }
        sr = wsum(sr); sz = wsum(sz); sn = wsum(sn);
        if (lane == 0) {
            float r = sigm(sr + bi0r + A0);
            float z = sigm(sz + bi0z + A1);
            float n = tanha(sn + bi0n + r * A2);
            g_h0[e] = (1.0f - z) * n + z * s_hn[e];
        }
    }

    gbar1();   // h0 visible

    // ---- GRU layer 1: register Wih1 x g_h0 (direct L2 read) ----
    if (act) {
        float sr = 0.f, sz = 0.f, sn = 0.f;
#pragma unroll
        for (int i = 0; i < 5; i++) {
            int k = lane + 32 * i;
            float x = (k < GH) ? g_h0[k] : 0.f;
            sr = fmaf(w1r[i], x, sr);
            sz = fmaf(w1z[i], x, sz);
            sn = fmaf(w1n[i], x, sn);
        }
        sr = wsum(sr); sz = wsum(sz); sn = wsum(sn);
        if (lane == 0) {
            float r = sigm(sr + bi1r + B0);
            float z = sigm(sz + bi1z + B1);
            float n = tanha(sn + bi1n + r * B2);
            g_h1[e] = (1.0f - z) * n + z * s_hn[GH + e];
        }
    }

    // ---- barrier 2: arrive-and-exit (only head block waits) ----
    __threadfence();
    __syncthreads();
    if (blockIdx.x != HEADB) {
        if (t == 0) atomicAdd(&g_cnt2, 1u);
        return;
    }
    if (t == 0) {
        volatile unsigned* c = &g_cnt2;
        while (*c != NB - 1u) { }
        g_cnt2 = 0;                 // reset for next graph replay
        __threadfence();
    }
    __syncthreads();
    __threadfence();

    // ---- output head (weights in smem; 16 warps) ----
    for (int i = t; i < GH; i += NT) s_v[i] = g_h1[i];
    __syncthreads();
    for (int r = lw; r < 40; r += WPB) {
        const float* w = &s_w2a[r * GH];
        float s = 0.f;
#pragma unroll 5
        for (int k = lane; k < GH; k += 32) s = fmaf(w[k], s_v[k], s);
        s = wsum(s);
        if (lane == 0) s_hid[r] = fmaxf(s + s_b2a[r], 0.0f);
    }
    __syncthreads();
    if (t < 10) {
        const float* w = &s_w2b[t * 40];
        float s = s_b2b[t];
#pragma unroll
        for (int k = 0; k < 40; k++) s = fmaf(w[k], s_hid[k], s);
        out[t] = s;
    }
}

extern "C" void kernel_launch(void* const* d_in, const int* in_sizes, int n_in,
                              void* d_out, int out_size) {
    (void)in_sizes; (void)n_in; (void)out_size;
    kalmannet_kernel<<<NB, NT>>>(
        (const float*)d_in[0],  (const float*)d_in[1],
        (const float*)d_in[2],  (const float*)d_in[3],
        (const float*)d_in[4],  (const float*)d_in[5],
        (const float*)d_in[6],  (const float*)d_in[7],
        (const float*)d_in[8],  (const float*)d_in[9],
        (const float*)d_in[10], (const float*)d_in[11],
        (const float*)d_in[12], (const float*)d_in[13],
        (const float*)d_in[14], (const float*)d_in[15],
        (const float*)d_in[16], (const float*)d_in[17],
        (const float*)d_in[18],
        (float*)d_out);
}

// round 16
// speedup vs baseline: 1.1576x; 1.1576x over previous
#include <cuda_runtime.h>

// ---------------------------------------------------------------------------
// DNN_KalmanNet_SLAM — fused, latency-optimized, BARRIER-FREE.
// 10 blocks x 512 threads; warp e owns GRU element e for both layers.
// Grid barriers replaced by NaN-sentinel dataflow: g_h0/g_h1 words start as
// quiet-NaN; a producer's single 32-bit store of the finished value IS the
// signal; consumers volatile-poll until non-NaN. Head block resets the
// sentinel arrays before exit (deterministic across graph replays).
// ---------------------------------------------------------------------------

#define NB     10
#define NT     512
#define WPB    16
#define H1     560
#define GH     145
#define HEADB  (NB - 1)

#define QNAN 0x7fc00000u
#define N1  QNAN
#define N2  N1, N1
#define N4  N2, N2
#define N8  N4, N4
#define N16 N8, N8
#define N64 N16, N16, N16, N16
#define N128 N64, N64
// 145 = 128 + 16 + 1
__device__ unsigned g_h0_bits[GH] = { N128, N16, N1 };
__device__ unsigned g_h1_bits[GH] = { N128, N16, N1 };

__device__ __forceinline__ float wsum(float v) {
#pragma unroll
    for (int o = 16; o; o >>= 1) v += __shfl_down_sync(0xffffffffu, v, o);
    return v;
}
__device__ __forceinline__ float sigm(float x) { return 1.0f / (1.0f + __expf(-x)); }
__device__ __forceinline__ float tanha(float x) {
    float y; asm("tanh.approx.f32 %0, %1;" : "=f"(y) : "f"(x)); return y;
}

__global__ __launch_bounds__(NT, 1)
void kalmannet_kernel(
    const float* __restrict__ state_inno, const float* __restrict__ obs_inno,
    const float* __restrict__ diff_state, const float* __restrict__ diff_obs,
    const float* __restrict__ W1,   const float* __restrict__ b1,
    const float* __restrict__ Wih0, const float* __restrict__ Whh0,
    const float* __restrict__ bih0, const float* __restrict__ bhh0,
    const float* __restrict__ Wih1, const float* __restrict__ Whh1,
    const float* __restrict__ bih1, const float* __restrict__ bhh1,
    const float* __restrict__ W2a,  const float* __restrict__ b2a,
    const float* __restrict__ W2b,  const float* __restrict__ b2b,
    const float* __restrict__ hn,
    float* __restrict__ out)
{
    __shared__ __align__(16) float s_l1[H1];
    __shared__ float s_x[16];
    __shared__ float s_hn[2 * GH];
    __shared__ float s_v[GH + 8];
    __shared__ float s_hid[40];
    __shared__ float s_w2a[40 * GH];    // head block only
    __shared__ float s_w2b[10 * 40];    // head block only
    __shared__ float s_b2a[40];
    __shared__ float s_b2b[10];

    const int t    = threadIdx.x;
    const int lane = t & 31;
    const int lw   = t >> 5;
    const int e    = blockIdx.x * WPB + lw;
    const bool act = (e < GH);

    // ---- inputs ----
    if (t < 14) {
        float v;
        if      (t < 5)  v = state_inno[t];
        else if (t < 7)  v = obs_inno[t - 5];
        else if (t < 12) v = diff_state[t - 7];
        else             v = diff_obs[t - 12];
        s_x[t] = v;
    }
    for (int i = t; i < 2 * GH; i += NT) s_hn[i] = __ldg(hn + i);
    __syncthreads();

    // ---- l1 (redundant per block; direct row loads) ----
    for (int r = t; r < H1; r += NT) {
        const float* w = W1 + r * 14;
        float s = b1[r];
#pragma unroll
        for (int k = 0; k < 14; k++) s = fmaf(w[k], s_x[k], s);
        s_l1[r] = fmaxf(s, 0.0f);
    }

    // ---- head block: idle warps prefetch head weights into smem ----
    if (blockIdx.x == HEADB && lw >= 1) {
        for (int i = t - 32; i < 40 * GH; i += NT - 32) s_w2a[i] = W2a[i];
        if (lw == 1) {
            if (lane < 10) s_b2b[lane] = b2b[lane];
            for (int i = lane; i < 40; i += 32) s_b2a[i] = b2a[i];
        }
        if (lw >= 2) {
            for (int i = t - 64; i < 400; i += NT - 64) s_w2b[i] = W2b[i];
        }
    }

    // ---- prefetch Wih1 rows into registers (independent of h0) ----
    float w1r[5], w1z[5], w1n[5];
    if (act) {
        const float* pr = Wih1 + e * GH;
        const float* pz = Wih1 + (e + GH) * GH;
        const float* pn = Wih1 + (e + 2 * GH) * GH;
#pragma unroll
        for (int i = 0; i < 5; i++) {
            int k = lane + 32 * i;
            bool ok = (k < GH);
            w1r[i] = ok ? __ldg(pr + k) : 0.f;
            w1z[i] = ok ? __ldg(pz + k) : 0.f;
            w1n[i] = ok ? __ldg(pn + k) : 0.f;
        }
    }

    // ---- recurrent dots for BOTH layers (independent of l1/h0) ----
    float A0 = 0.f, A1 = 0.f, A2 = 0.f;
    float B0 = 0.f, B1 = 0.f, B2 = 0.f;
    float bi0r = 0.f, bi0z = 0.f, bi0n = 0.f;
    float bi1r = 0.f, bi1z = 0.f, bi1n = 0.f;
    if (act) {
        const float* q0r = Whh0 + e * GH;
        const float* q0z = Whh0 + (e + GH) * GH;
        const float* q0n = Whh0 + (e + 2 * GH) * GH;
        const float* q1r = Whh1 + e * GH;
        const float* q1z = Whh1 + (e + GH) * GH;
        const float* q1n = Whh1 + (e + 2 * GH) * GH;
#pragma unroll 5
        for (int k = lane; k < GH; k += 32) {
            float h0v = s_hn[k], h1v = s_hn[GH + k];
            A0 = fmaf(q0r[k], h0v, A0);
            A1 = fmaf(q0z[k], h0v, A1);
            A2 = fmaf(q0n[k], h0v, A2);
            B0 = fmaf(q1r[k], h1v, B0);
            B1 = fmaf(q1z[k], h1v, B1);
            B2 = fmaf(q1n[k], h1v, B2);
        }
        A0 = wsum(A0); A1 = wsum(A1); A2 = wsum(A2);
        B0 = wsum(B0); B1 = wsum(B1); B2 = wsum(B2);
        if (lane == 0) {
            A0 += bhh0[e];  A1 += bhh0[e + GH];  A2 += bhh0[e + 2 * GH];
            B0 += bhh1[e];  B1 += bhh1[e + GH];  B2 += bhh1[e + 2 * GH];
            bi0r = bih0[e]; bi0z = bih0[e + GH]; bi0n = bih0[e + 2 * GH];
            bi1r = bih1[e]; bi1z = bih1[e + GH]; bi1n = bih1[e + 2 * GH];
        }
    }
    __syncthreads();   // s_l1 ready

    // ---- GRU layer 0: Wih0 @ l1 (float4), then publish h0 (store==signal) ----
    if (act) {
        const float4* xr = (const float4*)s_l1;
        const float4* wr = (const float4*)(Wih0 + e * H1);
        const float4* wz = (const float4*)(Wih0 + (e + GH) * H1);
        const float4* wn = (const float4*)(Wih0 + (e + 2 * GH) * H1);
        float sr = 0.f, sz = 0.f, sn = 0.f;
#pragma unroll
        for (int i = 0; i < 5; i++) {
            int k = lane + 32 * i;
            if (k < H1 / 4) {
                float4 x = xr[k];
                float4 a = wr[k];
                sr += a.x * x.x + a.y * x.y + a.z * x.z + a.w * x.w;
                float4 b = wz[k];
                sz += b.x * x.x + b.y * x.y + b.z * x.z + b.w * x.w;
                float4 c = wn[k];
                sn += c.x * x.x + c.y * x.y + c.z * x.z + c.w * x.w;
            }
        }
        sr = wsum(sr); sz = wsum(sz); sn = wsum(sn);
        if (lane == 0) {
            float r = sigm(sr + bi0r + A0);
            float z = sigm(sz + bi0z + A1);
            float n = tanha(sn + bi0n + r * A2);
            float h0 = (1.0f - z) * n + z * s_hn[e];
            ((volatile unsigned*)g_h0_bits)[e] = __float_as_uint(h0);
        }
    }

    // ---- GRU layer 1: poll g_h0 words directly (data==signal), reg weights ----
    if (act) {
        unsigned b[5];
#pragma unroll
        for (int i = 0; i < 5; i++) b[i] = (lane + 32 * i < GH) ? QNAN : 0u;
        volatile unsigned* p = (volatile unsigned*)g_h0_bits;
        for (;;) {
            bool all = true;
#pragma unroll
            for (int i = 0; i < 5; i++) {
                int k = lane + 32 * i;
                if (k < GH && b[i] == QNAN) {
                    b[i] = p[k];
                    if (b[i] == QNAN) all = false;
                }
            }
            if (__all_sync(0xffffffffu, all)) break;
        }
        float sr = 0.f, sz = 0.f, sn = 0.f;
#pragma unroll
        for (int i = 0; i < 5; i++) {
            float x = __uint_as_float(b[i]);
            if (lane + 32 * i >= GH) x = 0.f;
            sr = fmaf(w1r[i], x, sr);
            sz = fmaf(w1z[i], x, sz);
            sn = fmaf(w1n[i], x, sn);
        }
        sr = wsum(sr); sz = wsum(sz); sn = wsum(sn);
        if (lane == 0) {
            float r = sigm(sr + bi1r + B0);
            float z = sigm(sz + bi1z + B1);
            float n = tanha(sn + bi1n + r * B2);
            float h1 = (1.0f - z) * n + z * s_hn[GH + e];
            ((volatile unsigned*)g_h1_bits)[e] = __float_as_uint(h1);
        }
    }

    // ---- non-head blocks are done ----
    if (blockIdx.x != HEADB) return;

    // ---- head: poll all h1 into smem (thread t polls word t) ----
    if (t < GH) {
        volatile unsigned* p = (volatile unsigned*)g_h1_bits;
        unsigned v;
        do { v = p[t]; } while (v == QNAN);
        s_v[t] = __uint_as_float(v);
    }
    __syncthreads();

    // ---- output head (weights already in smem; 16 warps) ----
    for (int r = lw; r < 40; r += WPB) {
        const float* w = &s_w2a[r * GH];
        float s = 0.f;
#pragma unroll 5
        for (int k = lane; k < GH; k += 32) s = fmaf(w[k], s_v[k], s);
        s = wsum(s);
        if (lane == 0) s_hid[r] = fmaxf(s + s_b2a[r], 0.0f);
    }
    __syncthreads();
    if (t < 10) {
        const float* w = &s_w2b[t * 40];
        float s = s_b2b[t];
#pragma unroll
        for (int k = 0; k < 40; k++) s = fmaf(w[k], s_hid[k], s);
        out[t] = s;
    }

    // ---- reset sentinels for next graph replay (safe: all h1 observed,
    //      so every block's g_h0 reads are complete; no reads of these
    //      arrays happen after this point in this launch) ----
    for (int i = t; i < GH; i += NT) {
        g_h0_bits[i] = QNAN;
        g_h1_bits[i] = QNAN;
    }
}

extern "C" void kernel_launch(void* const* d_in, const int* in_sizes, int n_in,
                              void* d_out, int out_size) {
    (void)in_sizes; (void)n_in; (void)out_size;
    kalmannet_kernel<<<NB, NT>>>(
        (const float*)d_in[0],  (const float*)d_in[1],
        (const float*)d_in[2],  (const float*)d_in[3],
        (const float*)d_in[4],  (const float*)d_in[5],
        (const float*)d_in[6],  (const float*)d_in[7],
        (const float*)d_in[8],  (const float*)d_in[9],
        (const float*)d_in[10], (const float*)d_in[11],
        (const float*)d_in[12], (const float*)d_in[13],
        (const float*)d_in[14], (const float*)d_in[15],
        (const float*)d_in[16], (const float*)d_in[17],
        (const float*)d_in[18],
        (float*)d_out);
}